// round 15
// baseline (speedup 1.0000x reference)
#include <cuda_runtime.h>
#include <cstdint>

#define THREADS 256
#define ROWS_PER_BLOCK 8

typedef unsigned long long ull;

// ---------------- SMEM layout (byte offsets) ----------------
#define SM_PERCP 0         // [56 kp][128 px] float2, SWZ1                 57344
#define SM_W1P   57344     // [56 kp][128 o ] float2, SWZ1                 57344
#define SM_HSP   114688    // [64 r ][128 px] float2, SWZ1 ^ KMASK(r)      65536
#define SM_PART  (114688 + 32768)   // partial dx: [16][128] float2
#define SM_W2P   180224    // [64 kp][32 c  ] float2                       16384
#define SM_NS    196608    // [32 c][136 px] float                         17408
#define SM_B1    214016
#define SM_B2    214528
#define SM_G     214656
#define SM_BETA  214784
#define SM_MU    214912
#define SM_RS    215424
#define SM_INV   215936
#define SM_TOTAL 216448

#define SWZ1(o) ((uint32_t)(o) ^ ((((uint32_t)(o)) >> 3) & 0x30u))
#define KMASK(r) ((((((uint32_t)(r)) >> 2) & 3u) << 4) ^ (((((uint32_t)(r)) >> 2) & 4u) << 6))

#define BARG() asm volatile("bar.sync 1, 128;" ::: "memory")

__device__ __forceinline__ void ffma2(ull& d, ull a, ull b) {
    asm("fma.rn.f32x2 %0, %1, %2, %0;" : "+l"(d) : "l"(a), "l"(b));
}
__device__ __forceinline__ void unpack2(ull p, float& lo, float& hi) {
    asm("mov.b64 {%0, %1}, %2;" : "=f"(lo), "=f"(hi) : "l"(p));
}

__device__ __forceinline__ float perc_val(const float* __restrict__ xb, int y, int m, int k) {
    if (k < 32) return xb[(k * 128 + y) * 128 + m];
    int kk = k - 32;
    int c = kk >> 3, s = kk & 7;
    int idx = s + (s >= 4 ? 1 : 0);
    int ki = idx / 3;
    int dy = ki - 1, dxx = idx - ki * 3 - 1;
    int yy = y + dy, xx = m + dxx;
    if ((unsigned)yy < 128u && (unsigned)xx < 128u)
        return xb[(c * 128 + yy) * 128 + xx];
    return 0.0f;
}

// GEMM1 operand load/fma macros (double-buffered)
#define G1_LOAD(A_, W_, b_) { ulonglong2 t;                                       \
    t = *(const ulonglong2*)(pp + (b_) + a_off[0]); A_[0]=t.x; A_[1]=t.y;         \
    t = *(const ulonglong2*)(pp + (b_) + a_off[1]); A_[2]=t.x; A_[3]=t.y;         \
    t = *(const ulonglong2*)(pp + (b_) + a_off[2]); A_[4]=t.x; A_[5]=t.y;         \
    t = *(const ulonglong2*)(pp + (b_) + a_off[3]); A_[6]=t.x; A_[7]=t.y;         \
    t = *(const ulonglong2*)(pw + (b_) + w_off[0]); W_[0]=t.x; W_[1]=t.y;         \
    t = *(const ulonglong2*)(pw + (b_) + w_off[1]); W_[2]=t.x; W_[3]=t.y;         \
    t = *(const ulonglong2*)(pw + (b_) + w_off[2]); W_[4]=t.x; W_[5]=t.y;         \
    t = *(const ulonglong2*)(pw + (b_) + w_off[3]); W_[6]=t.x; W_[7]=t.y; }

#define G1_FMA(A_, W_) {                                                          \
    _Pragma("unroll")                                                             \
    for (int i_ = 0; i_ < 8; ++i_)                                                \
        _Pragma("unroll")                                                         \
        for (int j_ = 0; j_ < 8; ++j_)                                            \
            ffma2(acc[i_ * 8 + j_], A_[i_], W_[j_]); }

// GEMM2 operand load/fma macros
#define G2_LOAD(A_, W_, kp_) { uint32_t km_ = KMASK(kp_);                         \
    uint32_t bb_ = (uint32_t)(kp_) * 1024; ulonglong2 t;                          \
    t = *(const ulonglong2*)(ph + bb_ + (g2_aoff[0] ^ km_)); A_[0]=t.x; A_[1]=t.y;\
    t = *(const ulonglong2*)(ph + bb_ + (g2_aoff[1] ^ km_)); A_[2]=t.x; A_[3]=t.y;\
    t = *(const ulonglong2*)(ph + bb_ + (g2_aoff[2] ^ km_)); A_[4]=t.x; A_[5]=t.y;\
    t = *(const ulonglong2*)(ph + bb_ + (g2_aoff[3] ^ km_)); A_[6]=t.x; A_[7]=t.y;\
    t = *(const ulonglong2*)(pw2 + (kp_) * 256);      W_[0]=t.x; W_[1]=t.y;       \
    t = *(const ulonglong2*)(pw2 + (kp_) * 256 + 16); W_[2]=t.x; W_[3]=t.y; }

#define G2_FMA(A_, W_) {                                                          \
    _Pragma("unroll")                                                             \
    for (int j_ = 0; j_ < 4; ++j_)                                                \
        _Pragma("unroll")                                                         \
        for (int i_ = 0; i_ < 8; ++i_)                                            \
            ffma2(acc2[j_ * 8 + i_], A_[i_], W_[j_]); }

extern __shared__ char smem[];

__global__ void __launch_bounds__(THREADS, 1)
cellnn_kernel(const float* __restrict__ x,
              const float* __restrict__ w1,
              const float* __restrict__ b1,
              const float* __restrict__ w2,
              const float* __restrict__ b2,
              const float* __restrict__ gamma,
              const float* __restrict__ beta,
              float* __restrict__ out)
{
    float* b1s  = (float*)(smem + SM_B1);
    float* b2s  = (float*)(smem + SM_B2);
    float* gs   = (float*)(smem + SM_G);
    float* bts  = (float*)(smem + SM_BETA);
    float* mus  = (float*)(smem + SM_MU);
    float* rss  = (float*)(smem + SM_RS);
    float* invs = (float*)(smem + SM_INV);
    float* ns   = (float*)(smem + SM_NS);

    const int tid  = threadIdx.x;
    const int lane = tid & 31;
    const int warp = tid >> 5;

    #pragma unroll
    for (int it = 0; it < 56; ++it) {
        int i = it * THREADS + tid;
        int k = i >> 7, o = i & 127;
        float v = w1[o * 112 + k];
        uint32_t a = (uint32_t)((k >> 1) * 1024) + SWZ1((uint32_t)(o * 8)) + (uint32_t)((k & 1) * 4);
        *(float*)(smem + SM_W1P + a) = v;
    }
    #pragma unroll
    for (int it = 0; it < 16; ++it) {
        int i = it * THREADS + tid;
        int k = i >> 5, c = i & 31;
        float v = w2[c * 128 + k];
        *(float*)(smem + SM_W2P + (k >> 1) * 256 + c * 8 + (k & 1) * 4) = v;
    }
    if (tid < 128) b1s[tid] = b1[tid];
    if (tid < 32) { b2s[tid] = b2[tid]; gs[tid] = gamma[tid]; bts[tid] = beta[tid]; }

    const int row0 = blockIdx.x * ROWS_PER_BLOCK;
    const int bi   = row0 >> 7;
    const int y0   = row0 & 127;
    const float* xb = x   + (size_t)bi * 32 * 128 * 128;
    float*       ob = out + (size_t)bi * 32 * 128 * 128;

    const int g1_p0 = ((warp & 3) * 4 + (lane & 3)) * 8;
    const int g1_o0 = ((warp >> 2) * 8 + (lane >> 2)) * 8;
    uint32_t a_off[4], w_off[4];
    #pragma unroll
    for (int c = 0; c < 4; ++c) {
        a_off[c] = SWZ1((uint32_t)(g1_p0 * 8 + c * 16));
        w_off[c] = SWZ1((uint32_t)(g1_o0 * 8 + c * 16));
    }
    uint32_t h_off[4][4];
    #pragma unroll
    for (int jp = 0; jp < 4; ++jp) {
        uint32_t r = (uint32_t)(g1_o0 / 2 + jp);
        uint32_t km = KMASK(r);
        #pragma unroll
        for (int c = 0; c < 4; ++c)
            h_off[jp][c] = r * 1024 + (SWZ1((uint32_t)(g1_p0 * 8 + c * 16)) ^ km);
    }

    const int g2_hh = warp >> 2;
    const int g2_p0 = ((warp & 3) * 4 + (lane & 3)) * 8;
    const int g2_c0 = (lane >> 2) * 4;
    uint32_t g2_aoff[4];
    #pragma unroll
    for (int c = 0; c < 4; ++c)
        g2_aoff[c] = SWZ1((uint32_t)(g2_p0 * 8 + c * 16));

    #pragma unroll
    for (int it = 0; it < 28; ++it) {
        int i = it * THREADS + tid;
        int kp = i >> 7, px = i & 127;
        float v0 = perc_val(xb, y0, px, 2 * kp);
        float v1 = perc_val(xb, y0, px, 2 * kp + 1);
        uint32_t a = (uint32_t)(kp * 1024) + SWZ1((uint32_t)(px * 8));
        *(float2*)(smem + SM_PERCP + a) = make_float2(v0, v1);
    }
    __syncthreads();

    for (int r8 = 0; r8 < ROWS_PER_BLOCK; ++r8) {
        const int y = y0 + r8;

        // ================= GEMM1: double-buffered =================
        {
            ull acc[64];
            #pragma unroll
            for (int i = 0; i < 64; ++i) acc[i] = 0ull;

            const char* pp = smem + SM_PERCP;
            const char* pw = smem + SM_W1P;
            ull Aa[8], Wa[8], Ab[8], Wb[8];
            G1_LOAD(Aa, Wa, 0u);
            uint32_t base = 0;
            #pragma unroll 1
            for (int kp = 0; kp < 54; kp += 2) {
                G1_LOAD(Ab, Wb, base + 1024u);
                G1_FMA(Aa, Wa);
                G1_LOAD(Aa, Wa, base + 2048u);
                G1_FMA(Ab, Wb);
                base += 2048u;
            }
            G1_LOAD(Ab, Wb, base + 1024u);   // kp = 55
            G1_FMA(Aa, Wa);                  // kp = 54
            G1_FMA(Ab, Wb);                  // kp = 55

            #pragma unroll
            for (int jp = 0; jp < 4; ++jp) {
                float be = b1s[g1_o0 + 2 * jp];
                float bo = b1s[g1_o0 + 2 * jp + 1];
                char* sb = smem + SM_HSP;
                #pragma unroll
                for (int c = 0; c < 4; ++c) {
                    float l, h;
                    float4 v;
                    unpack2(acc[(2 * c) * 8 + 2 * jp], l, h);
                    v.x = fmaxf(l + h + be, 0.0f);
                    unpack2(acc[(2 * c) * 8 + 2 * jp + 1], l, h);
                    v.y = fmaxf(l + h + bo, 0.0f);
                    unpack2(acc[(2 * c + 1) * 8 + 2 * jp], l, h);
                    v.z = fmaxf(l + h + be, 0.0f);
                    unpack2(acc[(2 * c + 1) * 8 + 2 * jp + 1], l, h);
                    v.w = fmaxf(l + h + bo, 0.0f);
                    *(float4*)(sb + h_off[jp][c]) = v;
                }
            }
        }
        __syncthreads();

        // ================= GEMM2 split-K: double-buffered =================
        ull acc2[32];
        #pragma unroll
        for (int i = 0; i < 32; ++i) acc2[i] = 0ull;

        float4 xres[4][2];
        if (warp < 4) {
            // prefetch residual early — latency hidden under GEMM2
            #pragma unroll
            for (int j = 0; j < 4; ++j) {
                const float* xr = xb + ((g2_c0 + j) * 128 + y) * 128 + g2_p0;
                xres[j][0] = *(const float4*)(xr);
                xres[j][1] = *(const float4*)(xr + 4);
            }
        }
        {
            const char* ph = smem + SM_HSP;
            const char* pw2 = smem + SM_W2P + g2_c0 * 8;
            const int kp0 = g2_hh * 32;
            ull Aa[8], Wa[4], Ab[8], Wb[4];
            G2_LOAD(Aa, Wa, kp0);
            #pragma unroll 1
            for (int kq = 0; kq < 30; kq += 2) {
                G2_LOAD(Ab, Wb, kp0 + kq + 1);
                G2_FMA(Aa, Wa);
                G2_LOAD(Aa, Wa, kp0 + kq + 2);
                G2_FMA(Ab, Wb);
            }
            G2_LOAD(Ab, Wb, kp0 + 31);
            G2_FMA(Aa, Wa);                  // kq = 30
            G2_FMA(Ab, Wb);                  // kq = 31
        }

        if (warp >= 4) {
            // group 1: collapse f32x2 pairs, store partials
            const int tid2 = tid - 128;
            char* pb = smem + SM_PART + tid2 * 8;
            #pragma unroll
            for (int j = 0; j < 4; ++j) {
                #pragma unroll
                for (int ii = 0; ii < 4; ++ii) {
                    float l0, h0, l1, h1;
                    unpack2(acc2[j * 8 + 2 * ii], l0, h0);
                    unpack2(acc2[j * 8 + 2 * ii + 1], l1, h1);
                    *(float2*)(pb + (j * 4 + ii) * 1024) = make_float2(l0 + h0, l1 + h1);
                }
            }
        }
        __syncthreads();

        // ================= phase 3: warp-specialized =================
        if (warp < 4) {
            const char* pb = smem + SM_PART + tid * 8;
            #pragma unroll
            for (int j = 0; j < 4; ++j) {
                int c = g2_c0 + j;
                float bj = b2s[c];
                float4 v0, v1;
                float l, h;
                float2 p0 = *(const float2*)(pb + (j * 4 + 0) * 1024);
                float2 p1 = *(const float2*)(pb + (j * 4 + 1) * 1024);
                float2 p2 = *(const float2*)(pb + (j * 4 + 2) * 1024);
                float2 p3 = *(const float2*)(pb + (j * 4 + 3) * 1024);
                unpack2(acc2[j * 8 + 0], l, h); v0.x = l + h + p0.x + bj + xres[j][0].x;
                unpack2(acc2[j * 8 + 1], l, h); v0.y = l + h + p0.y + bj + xres[j][0].y;
                unpack2(acc2[j * 8 + 2], l, h); v0.z = l + h + p1.x + bj + xres[j][0].z;
                unpack2(acc2[j * 8 + 3], l, h); v0.w = l + h + p1.y + bj + xres[j][0].w;
                unpack2(acc2[j * 8 + 4], l, h); v1.x = l + h + p2.x + bj + xres[j][1].x;
                unpack2(acc2[j * 8 + 5], l, h); v1.y = l + h + p2.y + bj + xres[j][1].y;
                unpack2(acc2[j * 8 + 6], l, h); v1.z = l + h + p3.x + bj + xres[j][1].z;
                unpack2(acc2[j * 8 + 7], l, h); v1.w = l + h + p3.y + bj + xres[j][1].w;
                *(float4*)(ns + c * 136 + g2_p0)     = v0;
                *(float4*)(ns + c * 136 + g2_p0 + 4) = v1;
            }
            BARG();

            {
                int p = tid;
                const float* np = ns + p;
                float v0 = np[0];
                float best = v0;
                int arg = 0;
                float sv = v0, qv = v0 * v0;
                #pragma unroll
                for (int c = 1; c < 10; ++c) {
                    float v = np[c * 136];
                    sv += v; qv = fmaf(v, v, qv);
                    if (v > best) { best = v; arg = c; }
                }
                float sh = 0.0f, qh = 0.0f;
                #pragma unroll
                for (int c = 10; c < 32; ++c) {
                    float v = np[c * 136];
                    sh += v; qh = fmaf(v, v, qh);
                }
                float f = (arg != 0) ? 1.0f : 0.0f;
                float s = sv + f * sh;
                float q = qv + f * qh;
                float mu = s * (1.0f / 32.0f);
                float var = q * (1.0f / 32.0f) - mu * mu;
                mus[p]  = mu;
                rss[p]  = rsqrtf(var + 1e-5f);
                invs[p] = f;
            }
            BARG();

            {
                int c = tid >> 2, q = tid & 3;
                int pbx = q * 32;
                float g = gs[c], bb = bts[c];
                #pragma unroll
                for (int q4 = 0; q4 < 8; ++q4) {
                    int p4 = pbx + q4 * 4;
                    float4 xv = *(float4*)(ns + c * 136 + p4);
                    float4 m4 = *(float4*)(mus + p4);
                    float4 r4 = *(float4*)(rss + p4);
                    if (c >= 10) {
                        float4 f4 = *(float4*)(invs + p4);
                        xv.x *= f4.x; xv.y *= f4.y; xv.z *= f4.z; xv.w *= f4.w;
                    }
                    float4 o4;
                    o4.x = (xv.x - m4.x) * r4.x * g + bb;
                    o4.y = (xv.y - m4.y) * r4.y * g + bb;
                    o4.z = (xv.z - m4.z) * r4.z * g + bb;
                    o4.w = (xv.w - m4.w) * r4.w * g + bb;
                    *(float4*)(ob + (c * 128 + y) * 128 + p4) = o4;
                }
            }
        } else if (r8 + 1 < ROWS_PER_BLOCK) {
            const int yn = y + 1;
            const int tid2 = tid & 127;
            #pragma unroll
            for (int it = 0; it < 56; ++it) {
                int i = it * 128 + tid2;
                int kp = i >> 7, px = i & 127;
                float v0 = perc_val(xb, yn, px, 2 * kp);
                float v1 = perc_val(xb, yn, px, 2 * kp + 1);
                uint32_t a = (uint32_t)(kp * 1024) + SWZ1((uint32_t)(px * 8));
                *(float2*)(smem + SM_PERCP + a) = make_float2(v0, v1);
            }
        }
        __syncthreads();
    }
}

extern "C" void kernel_launch(void* const* d_in, const int* in_sizes, int n_in,
                              void* d_out, int out_size)
{
    const float* x     = (const float*)d_in[0];
    const float* w1    = (const float*)d_in[1];
    const float* b1    = (const float*)d_in[2];
    const float* w2    = (const float*)d_in[3];
    const float* b2    = (const float*)d_in[4];
    const float* gamma = (const float*)d_in[5];
    const float* beta  = (const float*)d_in[6];
    float* out = (float*)d_out;

    cudaFuncSetAttribute(cellnn_kernel,
                         cudaFuncAttributeMaxDynamicSharedMemorySize, SM_TOTAL);

    cellnn_kernel<<<1024, THREADS, SM_TOTAL>>>(x, w1, b1, w2, b2, gamma, beta, out);
}

// round 16
// speedup vs baseline: 1.0329x; 1.0329x over previous
#include <cuda_runtime.h>
#include <cstdint>

#define THREADS 256
#define ROWS_PER_BLOCK 8

typedef unsigned long long ull;

// ---------------- SMEM layout (byte offsets) ----------------
#define SM_PERCP 0         // [56 kp][128 px] float2, SWZ1                 57344
#define SM_W1P   57344     // [56 kp][128 o ] float2, SWZ1                 57344
#define SM_HSP   114688    // [64 r ][128 px] float2, SWZ1 ^ KMASK(r)      65536
#define SM_PART  (114688 + 32768)   // partial dx: [16][128] float2
#define SM_W2P   180224    // [64 kp][32 c  ] float2                       16384
#define SM_NS    196608    // [32 c][136 px] float                         17408
#define SM_B1    214016
#define SM_B2    214528
#define SM_G     214656
#define SM_BETA  214784
#define SM_MU    214912
#define SM_RS    215424
#define SM_INV   215936
#define SM_TOTAL 216448

#define SWZ1(o) ((uint32_t)(o) ^ ((((uint32_t)(o)) >> 3) & 0x30u))
#define KMASK(r) ((((((uint32_t)(r)) >> 2) & 3u) << 4) ^ (((((uint32_t)(r)) >> 2) & 4u) << 6))

#define BARG()  asm volatile("bar.sync 1, 128;" ::: "memory")   // phase-3 group
#define BARH0() asm volatile("bar.sync 2, 128;" ::: "memory")   // warps 0-3: hsp rows 0-31
#define BARH1() asm volatile("bar.sync 3, 128;" ::: "memory")   // warps 4-7: hsp rows 32-63

__device__ __forceinline__ void ffma2(ull& d, ull a, ull b) {
    asm("fma.rn.f32x2 %0, %1, %2, %0;" : "+l"(d) : "l"(a), "l"(b));
}
__device__ __forceinline__ void unpack2(ull p, float& lo, float& hi) {
    asm("mov.b64 {%0, %1}, %2;" : "=f"(lo), "=f"(hi) : "l"(p));
}

__device__ __forceinline__ float perc_val(const float* __restrict__ xb, int y, int m, int k) {
    if (k < 32) return xb[(k * 128 + y) * 128 + m];
    int kk = k - 32;
    int c = kk >> 3, s = kk & 7;
    int idx = s + (s >= 4 ? 1 : 0);
    int ki = idx / 3;
    int dy = ki - 1, dxx = idx - ki * 3 - 1;
    int yy = y + dy, xx = m + dxx;
    if ((unsigned)yy < 128u && (unsigned)xx < 128u)
        return xb[(c * 128 + yy) * 128 + xx];
    return 0.0f;
}

extern __shared__ char smem[];

__global__ void __launch_bounds__(THREADS, 1)
cellnn_kernel(const float* __restrict__ x,
              const float* __restrict__ w1,
              const float* __restrict__ b1,
              const float* __restrict__ w2,
              const float* __restrict__ b2,
              const float* __restrict__ gamma,
              const float* __restrict__ beta,
              float* __restrict__ out)
{
    float* b1s  = (float*)(smem + SM_B1);
    float* b2s  = (float*)(smem + SM_B2);
    float* gs   = (float*)(smem + SM_G);
    float* bts  = (float*)(smem + SM_BETA);
    float* mus  = (float*)(smem + SM_MU);
    float* rss  = (float*)(smem + SM_RS);
    float* invs = (float*)(smem + SM_INV);
    float* ns   = (float*)(smem + SM_NS);

    const int tid  = threadIdx.x;
    const int lane = tid & 31;
    const int warp = tid >> 5;

    #pragma unroll
    for (int it = 0; it < 56; ++it) {
        int i = it * THREADS + tid;
        int k = i >> 7, o = i & 127;
        float v = w1[o * 112 + k];
        uint32_t a = (uint32_t)((k >> 1) * 1024) + SWZ1((uint32_t)(o * 8)) + (uint32_t)((k & 1) * 4);
        *(float*)(smem + SM_W1P + a) = v;
    }
    #pragma unroll
    for (int it = 0; it < 16; ++it) {
        int i = it * THREADS + tid;
        int k = i >> 5, c = i & 31;
        float v = w2[c * 128 + k];
        *(float*)(smem + SM_W2P + (k >> 1) * 256 + c * 8 + (k & 1) * 4) = v;
    }
    if (tid < 128) b1s[tid] = b1[tid];
    if (tid < 32) { b2s[tid] = b2[tid]; gs[tid] = gamma[tid]; bts[tid] = beta[tid]; }

    const int row0 = blockIdx.x * ROWS_PER_BLOCK;
    const int bi   = row0 >> 7;
    const int y0   = row0 & 127;
    const float* xb = x   + (size_t)bi * 32 * 128 * 128;
    float*       ob = out + (size_t)bi * 32 * 128 * 128;

    // GEMM1 mapping: thread 8px x 8o; warps 0-3 -> o 0-63, warps 4-7 -> o 64-127
    const int g1_p0 = ((warp & 3) * 4 + (lane & 3)) * 8;
    const int g1_o0 = ((warp >> 2) * 8 + (lane >> 2)) * 8;
    uint32_t a_off[4], w_off[4];
    #pragma unroll
    for (int c = 0; c < 4; ++c) {
        a_off[c] = SWZ1((uint32_t)(g1_p0 * 8 + c * 16));
        w_off[c] = SWZ1((uint32_t)(g1_o0 * 8 + c * 16));
    }

    // GEMM2 mapping (split-K): warp>>2 = kp half; group g reads rows written by itself
    const int g2_hh = warp >> 2;
    const int g2_p0 = ((warp & 3) * 4 + (lane & 3)) * 8;
    const int g2_c0 = (lane >> 2) * 4;

    #pragma unroll
    for (int it = 0; it < 28; ++it) {
        int i = it * THREADS + tid;
        int kp = i >> 7, px = i & 127;
        float v0 = perc_val(xb, y0, px, 2 * kp);
        float v1 = perc_val(xb, y0, px, 2 * kp + 1);
        uint32_t a = (uint32_t)(kp * 1024) + SWZ1((uint32_t)(px * 8));
        *(float2*)(smem + SM_PERCP + a) = make_float2(v0, v1);
    }
    __syncthreads();

    for (int r8 = 0; r8 < ROWS_PER_BLOCK; ++r8) {
        const int y = y0 + r8;

        // ================= GEMM1: all 8 warps, 8px x 8o =================
        {
            ull acc[64];
            #pragma unroll
            for (int i = 0; i < 64; ++i) acc[i] = 0ull;

            const char* pp = smem + SM_PERCP;
            const char* pw = smem + SM_W1P;
            #pragma unroll 2
            for (int kp = 0; kp < 56; ++kp) {
                uint32_t base = (uint32_t)kp << 10;
                ull Av[8], Wv[8];
                {
                    ulonglong2 t;
                    t = *(const ulonglong2*)(pp + base + a_off[0]); Av[0] = t.x; Av[1] = t.y;
                    t = *(const ulonglong2*)(pp + base + a_off[1]); Av[2] = t.x; Av[3] = t.y;
                    t = *(const ulonglong2*)(pp + base + a_off[2]); Av[4] = t.x; Av[5] = t.y;
                    t = *(const ulonglong2*)(pp + base + a_off[3]); Av[6] = t.x; Av[7] = t.y;
                    t = *(const ulonglong2*)(pw + base + w_off[0]); Wv[0] = t.x; Wv[1] = t.y;
                    t = *(const ulonglong2*)(pw + base + w_off[1]); Wv[2] = t.x; Wv[3] = t.y;
                    t = *(const ulonglong2*)(pw + base + w_off[2]); Wv[4] = t.x; Wv[5] = t.y;
                    t = *(const ulonglong2*)(pw + base + w_off[3]); Wv[6] = t.x; Wv[7] = t.y;
                }
                #pragma unroll
                for (int i = 0; i < 8; ++i)
                    #pragma unroll
                    for (int j = 0; j < 8; ++j)
                        ffma2(acc[i * 8 + j], Av[i], Wv[j]);
            }
            // epilogue: h = relu(lo+hi+b1); offsets recomputed here (not held live)
            #pragma unroll
            for (int jp = 0; jp < 4; ++jp) {
                float be = b1s[g1_o0 + 2 * jp];
                float bo = b1s[g1_o0 + 2 * jp + 1];
                uint32_t r = (uint32_t)(g1_o0 / 2 + jp);
                uint32_t km = KMASK(r);
                char* sb = smem + SM_HSP + r * 1024;
                #pragma unroll
                for (int c = 0; c < 4; ++c) {
                    float l, h;
                    float4 v;
                    unpack2(acc[(2 * c) * 8 + 2 * jp], l, h);
                    v.x = fmaxf(l + h + be, 0.0f);
                    unpack2(acc[(2 * c) * 8 + 2 * jp + 1], l, h);
                    v.y = fmaxf(l + h + bo, 0.0f);
                    unpack2(acc[(2 * c + 1) * 8 + 2 * jp], l, h);
                    v.z = fmaxf(l + h + be, 0.0f);
                    unpack2(acc[(2 * c + 1) * 8 + 2 * jp + 1], l, h);
                    v.w = fmaxf(l + h + bo, 0.0f);
                    *(float4*)(sb + (SWZ1((uint32_t)(g1_p0 * 8 + c * 16)) ^ km)) = v;
                }
            }
        }
        // half-block barrier: each GEMM2 group only needs its OWN half of hsp
        if (warp < 4) BARH0(); else BARH1();

        // ================= GEMM2 split-K: all 8 warps, half kp range each =========
        ull acc2[32];
        #pragma unroll
        for (int i = 0; i < 32; ++i) acc2[i] = 0ull;
        {
            const char* ph = smem + SM_HSP;
            const char* pw2 = smem + SM_W2P + g2_c0 * 8;
            const int kp0 = g2_hh * 32;
            uint32_t aof[4];
            #pragma unroll
            for (int c = 0; c < 4; ++c)
                aof[c] = SWZ1((uint32_t)(g2_p0 * 8 + c * 16));
            #pragma unroll 4
            for (int kq = 0; kq < 32; ++kq) {
                int kp = kp0 + kq;
                uint32_t km = KMASK(kp);
                uint32_t base = (uint32_t)(kp * 1024);
                ull Av[8], Wv[4];
                {
                    ulonglong2 t;
                    t = *(const ulonglong2*)(ph + base + (aof[0] ^ km)); Av[0] = t.x; Av[1] = t.y;
                    t = *(const ulonglong2*)(ph + base + (aof[1] ^ km)); Av[2] = t.x; Av[3] = t.y;
                    t = *(const ulonglong2*)(ph + base + (aof[2] ^ km)); Av[4] = t.x; Av[5] = t.y;
                    t = *(const ulonglong2*)(ph + base + (aof[3] ^ km)); Av[6] = t.x; Av[7] = t.y;
                    t = *(const ulonglong2*)(pw2 + kp * 256);      Wv[0] = t.x; Wv[1] = t.y;
                    t = *(const ulonglong2*)(pw2 + kp * 256 + 16); Wv[2] = t.x; Wv[3] = t.y;
                }
                #pragma unroll
                for (int j = 0; j < 4; ++j)
                    #pragma unroll
                    for (int i = 0; i < 8; ++i)
                        ffma2(acc2[j * 8 + i], Av[i], Wv[j]);
            }
        }

        float4 xres[4][2];
        if (warp < 4) {
            // prefetch residual from global (latency lands during barrier wait)
            #pragma unroll
            for (int j = 0; j < 4; ++j) {
                const float* xr = xb + ((g2_c0 + j) * 128 + y) * 128 + g2_p0;
                xres[j][0] = *(const float4*)(xr);
                xres[j][1] = *(const float4*)(xr + 4);
            }
        } else {
            // group 1: collapse f32x2 pairs, store partials
            const int tid2 = tid - 128;
            char* pb = smem + SM_PART + tid2 * 8;
            #pragma unroll
            for (int j = 0; j < 4; ++j) {
                #pragma unroll
                for (int ii = 0; ii < 4; ++ii) {
                    float l0, h0, l1, h1;
                    unpack2(acc2[j * 8 + 2 * ii], l0, h0);
                    unpack2(acc2[j * 8 + 2 * ii + 1], l1, h1);
                    *(float2*)(pb + (j * 4 + ii) * 1024) = make_float2(l0 + h0, l1 + h1);
                }
            }
        }
        __syncthreads();

        // ================= phase 3: warp-specialized =================
        if (warp < 4) {
            const char* pb = smem + SM_PART + tid * 8;
            #pragma unroll
            for (int j = 0; j < 4; ++j) {
                int c = g2_c0 + j;
                float bj = b2s[c];
                float4 v0, v1;
                float l, h;
                float2 p0 = *(const float2*)(pb + (j * 4 + 0) * 1024);
                float2 p1 = *(const float2*)(pb + (j * 4 + 1) * 1024);
                float2 p2 = *(const float2*)(pb + (j * 4 + 2) * 1024);
                float2 p3 = *(const float2*)(pb + (j * 4 + 3) * 1024);
                unpack2(acc2[j * 8 + 0], l, h); v0.x = l + h + p0.x + bj + xres[j][0].x;
                unpack2(acc2[j * 8 + 1], l, h); v0.y = l + h + p0.y + bj + xres[j][0].y;
                unpack2(acc2[j * 8 + 2], l, h); v0.z = l + h + p1.x + bj + xres[j][0].z;
                unpack2(acc2[j * 8 + 3], l, h); v0.w = l + h + p1.y + bj + xres[j][0].w;
                unpack2(acc2[j * 8 + 4], l, h); v1.x = l + h + p2.x + bj + xres[j][1].x;
                unpack2(acc2[j * 8 + 5], l, h); v1.y = l + h + p2.y + bj + xres[j][1].y;
                unpack2(acc2[j * 8 + 6], l, h); v1.z = l + h + p3.x + bj + xres[j][1].z;
                unpack2(acc2[j * 8 + 7], l, h); v1.w = l + h + p3.y + bj + xres[j][1].w;
                *(float4*)(ns + c * 136 + g2_p0)     = v0;
                *(float4*)(ns + c * 136 + g2_p0 + 4) = v1;
            }
            BARG();

            {
                int p = tid;
                const float* np = ns + p;
                float v0 = np[0];
                float best = v0;
                int arg = 0;
                float sv = v0, qv = v0 * v0;
                #pragma unroll
                for (int c = 1; c < 10; ++c) {
                    float v = np[c * 136];
                    sv += v; qv = fmaf(v, v, qv);
                    if (v > best) { best = v; arg = c; }
                }
                float sh = 0.0f, qh = 0.0f;
                #pragma unroll
                for (int c = 10; c < 32; ++c) {
                    float v = np[c * 136];
                    sh += v; qh = fmaf(v, v, qh);
                }
                float f = (arg != 0) ? 1.0f : 0.0f;
                float s = sv + f * sh;
                float q = qv + f * qh;
                float mu = s * (1.0f / 32.0f);
                float var = q * (1.0f / 32.0f) - mu * mu;
                mus[p]  = mu;
                rss[p]  = rsqrtf(var + 1e-5f);
                invs[p] = f;
            }
            BARG();

            {
                int c = tid >> 2, q = tid & 3;
                int pbx = q * 32;
                float g = gs[c], bb = bts[c];
                #pragma unroll
                for (int q4 = 0; q4 < 8; ++q4) {
                    int p4 = pbx + q4 * 4;
                    float4 xv = *(float4*)(ns + c * 136 + p4);
                    float4 m4 = *(float4*)(mus + p4);
                    float4 r4 = *(float4*)(rss + p4);
                    if (c >= 10) {
                        float4 f4 = *(float4*)(invs + p4);
                        xv.x *= f4.x; xv.y *= f4.y; xv.z *= f4.z; xv.w *= f4.w;
                    }
                    float4 o4;
                    o4.x = (xv.x - m4.x) * r4.x * g + bb;
                    o4.y = (xv.y - m4.y) * r4.y * g + bb;
                    o4.z = (xv.z - m4.z) * r4.z * g + bb;
                    o4.w = (xv.w - m4.w) * r4.w * g + bb;
                    *(float4*)(ob + (c * 128 + y) * 128 + p4) = o4;
                }
            }
        } else if (r8 + 1 < ROWS_PER_BLOCK) {
            const int yn = y + 1;
            const int tid2 = tid & 127;
            #pragma unroll
            for (int it = 0; it < 56; ++it) {
                int i = it * 128 + tid2;
                int kp = i >> 7, px = i & 127;
                float v0 = perc_val(xb, yn, px, 2 * kp);
                float v1 = perc_val(xb, yn, px, 2 * kp + 1);
                uint32_t a = (uint32_t)(kp * 1024) + SWZ1((uint32_t)(px * 8));
                *(float2*)(smem + SM_PERCP + a) = make_float2(v0, v1);
            }
        }
        __syncthreads();
    }
}

extern "C" void kernel_launch(void* const* d_in, const int* in_sizes, int n_in,
                              void* d_out, int out_size)
{
    const float* x     = (const float*)d_in[0];
    const float* w1    = (const float*)d_in[1];
    const float* b1    = (const float*)d_in[2];
    const float* w2    = (const float*)d_in[3];
    const float* b2    = (const float*)d_in[4];
    const float* gamma = (const float*)d_in[5];
    const float* beta  = (const float*)d_in[6];
    float* out = (float*)d_out;

    cudaFuncSetAttribute(cellnn_kernel,
                         cudaFuncAttributeMaxDynamicSharedMemorySize, SM_TOTAL);

    cellnn_kernel<<<1024, THREADS, SM_TOTAL>>>(x, w1, b1, w2, b2, gamma, beta, out);
}